// round 7
// baseline (speedup 1.0000x reference)
#include <cuda_runtime.h>
#include <cuda_fp16.h>
#include <cstring>

#define B_    2
#define C_    32
#define H_    128
#define W_    256
#define MAXD  12
#define D_    23            // 2*MAXD - 1
#define HW    (H_ * W_)
#define WT    256           // threads per CTA (full row)
#define NG    8             // channel groups of 4: (2g, 2g+1, 2g+16, 2g+17)
#define PADL  75            // floor(w - disp - 11) >= -75
#define SW    345           // 75 left + 256 + 14 right pad
#define NSPL  4             // disparity splits: 6/6/6/5
#define DG    6
#define TAPS  7             // DG + 1

__device__ __forceinline__ __half2 u2h2(unsigned u) {
    __half2 r; memcpy(&r, &u, 4); return r;
}

// out[b,d,h,w] = sum_c |feat_l[b,c,h,w] - (w0*fr[c,x0+d] + w1*fr[c,x0+d+1])|
// x0 = floor(w - disp) - (MAXD-1); fractional weight constant across d.
// feat_r row staged zero-padded in smem as 8B quads of 4 fp16 channels
// (one LDS.64 = one tap for 4 channels). 4-way disparity split + full-row
// 256-thread CTAs: 1024 CTAs x 8 warps = ~55 warps/SM so the LDS pipe is
// actually driven (R6 measured 56% L1 util at 25 warps/SM). half2 interp,
// fp32 flush every 4 channels (rel_err ~1.5e-4, tol 1e-3).
__global__ __launch_bounds__(WT)
void cost_volume_kernel(const float* __restrict__ feat_l,
                        const float* __restrict__ feat_r,
                        const float* __restrict__ disp,
                        float* __restrict__ out)
{
    __shared__ __align__(16) __half2 s_q[NG][SW][2];   // 22080 B

    const int spl = blockIdx.x;          // 0..3
    const int h   = blockIdx.y;
    const int b   = blockIdx.z;
    const int tid = threadIdx.x;
    const int w   = tid;
    const int dlo = spl * DG;            // 0, 6, 12, 18

    // ---- stage zero-padded feat_r row as 4-channel quads ----
    {
        const float* fr0 = feat_r + (((long)b * C_) * H_ + h) * W_;
        #pragma unroll
        for (int s = 0; s < 2; s++) {
            const int i = tid + s * WT;
            if (i < SW) {
                const int gx = i - PADL;
                const bool v = (gx >= 0) & (gx < W_);
                const int gxc = v ? gx : 0;
                #pragma unroll
                for (int g = 0; g < NG; g++) {
                    const float c0  = v ? __ldg(fr0 + (2*g)      * HW + gxc) : 0.0f;
                    const float c1  = v ? __ldg(fr0 + (2*g + 1)  * HW + gxc) : 0.0f;
                    const float c16 = v ? __ldg(fr0 + (2*g + 16) * HW + gxc) : 0.0f;
                    const float c17 = v ? __ldg(fr0 + (2*g + 17) * HW + gxc) : 0.0f;
                    s_q[g][i][0] = __floats2half2_rn(c0, c16);
                    s_q[g][i][1] = __floats2half2_rn(c1, c17);
                }
            }
        }
    }
    __syncthreads();

    // ---- per-thread interpolation setup ----
    const float dval = __ldg(disp + ((long)b * H_ + h) * W_ + w);
    const float px0  = ((float)w - dval) - (float)(MAXD - 1);
    const float xf   = floorf(px0);
    const float w1   = px0 - xf;          // right-neighbor weight (const over d)
    const float w0   = 1.0f - w1;
    int x0l = (int)xf + PADL;             // in [w, w+64]
    x0l = max(0, min(SW - 25, x0l));      // xs + TAPS <= 345 for all splits
    const int xs = x0l + dlo;

    const __half2 nw0 = __float2half2_rn(-w0);
    const __half2 nw1 = __float2half2_rn(-w1);

    float accf[DG];
    #pragma unroll
    for (int d = 0; d < DG; d++) accf[d] = 0.0f;

    const float* fl0 = feat_l + (((long)b * C_) * H_ + h) * W_ + w;

    #pragma unroll 1
    for (int gg = 0; gg < NG / 2; gg++) {          // 4 outer groups (8 channels)
        __half2 acc2[DG];
        #pragma unroll
        for (int d = 0; d < DG; d++) acc2[d] = __float2half2_rn(0.0f);

        #pragma unroll
        for (int sub = 0; sub < 2; sub++) {
            const int g = gg * 2 + sub;
            const float fa  = __ldg(fl0 + (2*g)      * HW);
            const float fb  = __ldg(fl0 + (2*g + 1)  * HW);
            const float fa2 = __ldg(fl0 + (2*g + 16) * HW);
            const float fb2 = __ldg(fl0 + (2*g + 17) * HW);
            const __half2 flcA = __floats2half2_rn(fa, fa2);
            const __half2 flcB = __floats2half2_rn(fb, fb2);

            const uint2* row = reinterpret_cast<const uint2*>(&s_q[g][xs][0]);
            uint2 t[TAPS];
            #pragma unroll
            for (int j = 0; j < TAPS; j++) t[j] = row[j];   // 7 x LDS.64

            #pragma unroll
            for (int d = 0; d < DG; d++) {
                __half2 u0 = __hfma2(u2h2(t[d].x),     nw0, flcA);
                u0         = __hfma2(u2h2(t[d + 1].x), nw1, u0);
                __half2 u1 = __hfma2(u2h2(t[d].y),     nw0, flcB);
                u1         = __hfma2(u2h2(t[d + 1].y), nw1, u1);
                acc2[d] = __hadd2(acc2[d], __hadd2(__habs2(u0), __habs2(u1)));
            }
        }

        // flush packed half accumulators to fp32
        #pragma unroll
        for (int d = 0; d < DG; d++) {
            float2 f = __half22float2(acc2[d]);
            accf[d] += f.x + f.y;
        }
    }

    // ---- write out[b, dlo+d, h, w] (last split writes 5) ----
    float* orow = out + (((long)b * D_ + dlo) * H_ + h) * W_ + w;
    #pragma unroll
    for (int d = 0; d < DG; d++)
        if (dlo + d < D_) orow[(long)d * HW] = accf[d];
}

extern "C" void kernel_launch(void* const* d_in, const int* in_sizes, int n_in,
                              void* d_out, int out_size)
{
    (void)in_sizes; (void)n_in; (void)out_size;
    const float* feat_l = (const float*)d_in[0];
    const float* feat_r = (const float*)d_in[1];
    const float* disp   = (const float*)d_in[2];
    float* out = (float*)d_out;

    dim3 grid(NSPL, H_, B_);    // 1024 CTAs x 8 warps
    cost_volume_kernel<<<grid, WT>>>(feat_l, feat_r, disp, out);
}

// round 8
// speedup vs baseline: 1.0019x; 1.0019x over previous
#include <cuda_runtime.h>
#include <cuda_fp16.h>
#include <cstring>

#define B_    2
#define C_    32
#define H_    128
#define W_    256
#define MAXD  12
#define D_    23            // 2*MAXD - 1
#define HW    (H_ * W_)
#define WT    128           // threads per CTA (half row)
#define NG    8             // channel quads: (2g, 2g+1, 2g+16, 2g+17)
#define SW2   220           // window: 76 left halo + 128 + 16 right
#define HALO  76
#define DG    12            // disparities per split (d=11 computed by both)
#define TAPS  13            // DG + 1
#define NBLK  55            // SW2 / 4 fill position-blocks

__device__ __forceinline__ __half2 u2h2(unsigned u) {
    __half2 r; memcpy(&r, &u, 4); return r;
}

// out[b,d,h,w] = sum_c |feat_l[b,c,h,w] - (w0*fr[c,x0+d] + w1*fr[c,x0+d+1])|
// R6 structure (fp16 4-channel quads, LDS.64 gather, 2 d-splits x 2 halves =
// 1024 CTAs) with the two measured overheads removed:
//  - fill vectorized: LDG.128/STS.128 (window blocks are exactly 4-aligned,
//    edge blocks fully in/out of [0,W)), ~2x fewer fill issue slots
//  - all 32 feat_l loads hoisted before the gather loop into 16 half2 regs:
//    no in-loop LDG latency, groups are pure LDS+FMA
__global__ __launch_bounds__(WT)
void cost_volume_kernel(const float* __restrict__ feat_l,
                        const float* __restrict__ feat_r,
                        const float* __restrict__ disp,
                        float* __restrict__ out)
{
    __shared__ __align__(16) uint2 s_q[NG][SW2];   // 14080 B

    const int xb    = blockIdx.x;        // 0..3 : (spl<<1)|half
    const int half_ = xb & 1;
    const int spl   = xb >> 1;
    const int h     = blockIdx.y;
    const int b     = blockIdx.z;
    const int tid   = threadIdx.x;
    const int W0    = half_ * WT;
    const int base  = W0 - HALO;         // global x of window index 0 (mult of 4)
    const int dlo   = spl * 11;          // 0 or 11

    // ---- vectorized fill: 440 tasks of (quad g, 4 window positions) ----
    {
        const float* fr0 = feat_r + (((long)b * C_) * H_ + h) * W_;
        #pragma unroll
        for (int it = 0; it < 4; it++) {
            const int task = tid + it * WT;
            if (task < NG * NBLK) {
                const int g  = task / NBLK;
                const int i0 = (task % NBLK) * 4;
                const int gx = base + i0;
                float4 f0, f1, f2, f3;
                if ((gx >= 0) & (gx < W_)) {   // blocks are fully valid or fully OOB
                    f0 = *reinterpret_cast<const float4*>(fr0 + (2*g)      * HW + gx);
                    f1 = *reinterpret_cast<const float4*>(fr0 + (2*g + 1)  * HW + gx);
                    f2 = *reinterpret_cast<const float4*>(fr0 + (2*g + 16) * HW + gx);
                    f3 = *reinterpret_cast<const float4*>(fr0 + (2*g + 17) * HW + gx);
                } else {
                    f0 = f1 = f2 = f3 = make_float4(0.f, 0.f, 0.f, 0.f);
                }
                __half2 p0 = __floats2half2_rn(f0.x, f2.x), q0 = __floats2half2_rn(f1.x, f3.x);
                __half2 p1 = __floats2half2_rn(f0.y, f2.y), q1 = __floats2half2_rn(f1.y, f3.y);
                __half2 p2 = __floats2half2_rn(f0.z, f2.z), q2 = __floats2half2_rn(f1.z, f3.z);
                __half2 p3 = __floats2half2_rn(f0.w, f2.w), q3 = __floats2half2_rn(f1.w, f3.w);
                uint4* dst = reinterpret_cast<uint4*>(&s_q[g][i0]);
                uint4 o0, o1;
                memcpy(&o0.x, &p0, 4); memcpy(&o0.y, &q0, 4);
                memcpy(&o0.z, &p1, 4); memcpy(&o0.w, &q1, 4);
                memcpy(&o1.x, &p2, 4); memcpy(&o1.y, &q2, 4);
                memcpy(&o1.z, &p3, 4); memcpy(&o1.w, &q3, 4);
                dst[0] = o0;
                dst[1] = o1;
            }
        }
    }

    // ---- per-thread interpolation setup (overlaps fill LDGs) ----
    const int   w    = W0 + tid;
    const float dval = __ldg(disp + ((long)b * H_ + h) * W_ + w);
    const float px0  = ((float)w - dval) - (float)(MAXD - 1);
    const float xf   = floorf(px0);
    const float w1   = px0 - xf;
    const float w0   = 1.0f - w1;
    int x0l = (int)xf - base;
    x0l = max(0, min(SW2 - 24, x0l));
    const int xs = x0l + dlo;

    const __half2 nw0 = __float2half2_rn(-w0);
    const __half2 nw1 = __float2half2_rn(-w1);

    // ---- hoist all 32 feat_l values into 16 half2 regs ----
    __half2 flc[NG][2];
    {
        const float* fl0 = feat_l + (((long)b * C_) * H_ + h) * W_ + w;
        #pragma unroll
        for (int g = 0; g < NG; g++) {
            const float fa  = __ldg(fl0 + (2*g)      * HW);
            const float fb  = __ldg(fl0 + (2*g + 1)  * HW);
            const float fa2 = __ldg(fl0 + (2*g + 16) * HW);
            const float fb2 = __ldg(fl0 + (2*g + 17) * HW);
            flc[g][0] = __floats2half2_rn(fa, fa2);
            flc[g][1] = __floats2half2_rn(fb, fb2);
        }
    }

    __syncthreads();

    float accf[DG];
    #pragma unroll
    for (int d = 0; d < DG; d++) accf[d] = 0.0f;

    #pragma unroll 1
    for (int gg = 0; gg < NG / 2; gg++) {          // 4 outer groups (8 channels)
        __half2 acc2[DG];
        #pragma unroll
        for (int d = 0; d < DG; d++) acc2[d] = __float2half2_rn(0.0f);

        #pragma unroll
        for (int sub = 0; sub < 2; sub++) {
            const int g = gg * 2 + sub;
            const uint2* row = &s_q[g][xs];
            uint2 t[TAPS];
            #pragma unroll
            for (int j = 0; j < TAPS; j++) t[j] = row[j];   // 13 x LDS.64

            const __half2 fA = flc[g][0];
            const __half2 fB = flc[g][1];
            #pragma unroll
            for (int d = 0; d < DG; d++) {
                __half2 u0 = __hfma2(u2h2(t[d].x),     nw0, fA);
                u0         = __hfma2(u2h2(t[d + 1].x), nw1, u0);
                __half2 u1 = __hfma2(u2h2(t[d].y),     nw0, fB);
                u1         = __hfma2(u2h2(t[d + 1].y), nw1, u1);
                acc2[d] = __hadd2(acc2[d], __hadd2(__habs2(u0), __habs2(u1)));
            }
        }

        #pragma unroll
        for (int d = 0; d < DG; d++) {
            float2 f = __half22float2(acc2[d]);
            accf[d] += f.x + f.y;
        }
    }

    // ---- write out[b, dlo+d, h, w] (d=11 written by both splits, same value) ----
    float* orow = out + (((long)b * D_ + dlo) * H_ + h) * W_ + w;
    #pragma unroll
    for (int d = 0; d < DG; d++)
        orow[(long)d * HW] = accf[d];
}

extern "C" void kernel_launch(void* const* d_in, const int* in_sizes, int n_in,
                              void* d_out, int out_size)
{
    (void)in_sizes; (void)n_in; (void)out_size;
    const float* feat_l = (const float*)d_in[0];
    const float* feat_r = (const float*)d_in[1];
    const float* disp   = (const float*)d_in[2];
    float* out = (float*)d_out;

    dim3 grid(4, H_, B_);     // 2 halves x 2 d-splits = 1024 CTAs
    cost_volume_kernel<<<grid, WT>>>(feat_l, feat_r, disp, out);
}